// round 15
// baseline (speedup 1.0000x reference)
#include <cuda_runtime.h>
#include <math.h>
#include <stdint.h>

// Problem constants
#define NBT    16384    // B * n_blocks (4 * 4096)
#define CDIM   256      // model channels
#define NB     4096     // blocks (tokens) per batch
#define BATCH  4
#define NLAYERS 4
#define KC320  320      // Eigen TensorContractionBlocking kc cap
#define NPANEL 13       // ceil(4096/320)

#define BK  64          // k-slice per smem stage (320 % 64 == 0)
#define LDW 132         // smem row stride in floats (528B, 16B-aligned)
#define TILE_SMEM (2 * BK * LDW * 4)   // 67584 B -> dynamic smem

typedef unsigned long long u64;

// ---------------- scratch (device globals; no runtime allocation) ----------
__device__ float g_h [NBT * CDIM];
__device__ float g_hp[NBT * CDIM];
__device__ float g_k [NBT * CDIM];
__device__ float g_q [NBT * CDIM];
__device__ float g_v [NBT * CDIM];
__device__ float g_m [(size_t)BATCH * NB * NB];        // 268 MB scores
__device__ float g_pp[(size_t)NPANEL * NBT * CDIM];    // 218 MB av panel partials

// ---------------------------------------------------------------------------
// f32x2 packed helpers: two INDEPENDENT IEEE RN ops per instruction ->
// bitwise identical to scalar fmaf / __fadd_rn on each half.
// ---------------------------------------------------------------------------
__device__ __forceinline__ u64 pack2(float lo, float hi)
{ u64 r; asm("mov.b64 %0, {%1,%2};" : "=l"(r) : "f"(lo), "f"(hi)); return r; }
__device__ __forceinline__ u64 fma2(u64 a, u64 b, u64 c)
{ u64 d; asm("fma.rn.f32x2 %0, %1, %2, %3;" : "=l"(d) : "l"(a), "l"(b), "l"(c)); return d; }

// ---------------------------------------------------------------------------
// XLA:CPU llvm_ir::EmitFastTanh, with_fma=true: clamp +-7.99881172180175781,
// FMA Horner, RN divide, |x|<4e-4 -> x (select on unclamped input).
// ---------------------------------------------------------------------------
__device__ __forceinline__ float tanh_xla(float x)
{
    const float kClamp = 7.99881172180175781f;
    float xc = fminf(fmaxf(x, -kClamp), kClamp);
    float x2 = xc * xc;
    float p = -2.76076847742355e-16f;
    p = fmaf(x2, p,  2.00018790482477e-13f);
    p = fmaf(x2, p, -8.60467152213735e-11f);
    p = fmaf(x2, p,  5.12229709037114e-08f);
    p = fmaf(x2, p,  1.48572235717979e-05f);
    p = fmaf(x2, p,  6.37261928875436e-04f);
    p = fmaf(x2, p,  4.89352455891786e-03f);
    p = xc * p;
    float q = 1.19825839466702e-06f;
    q = fmaf(x2, q, 1.18534705686654e-04f);
    q = fmaf(x2, q, 2.26843463243900e-03f);
    q = fmaf(x2, q, 4.89352518554385e-03f);
    float r = __fdiv_rn(p, q);
    return (fabsf(x) < 0.0004f) ? x : r;
}

// 8x8 microtile step: A broadcast via 2x LDS.128 + 8 pack movs, B pairs via
// 2x LDS.128. Row map i: (i<4 ? ty*4+i : 64+ty*4+i-4); col pairs j:
// {tx*4, tx*4+2, 64+tx*4, 64+tx*4+2}. Single ascending chain per output.
#define MICRO_STEP(AsRow, BsRow)                                          \
    do {                                                                  \
        float4 alo = *(const float4*)&(AsRow)[ty << 2];                   \
        float4 ahi = *(const float4*)&(AsRow)[64 + (ty << 2)];            \
        ulonglong2 blo = *(const ulonglong2*)&(BsRow)[tx << 2];           \
        ulonglong2 bhi = *(const ulonglong2*)&(BsRow)[64 + (tx << 2)];    \
        u64 b2[4] = {blo.x, blo.y, bhi.x, bhi.y};                         \
        float am[8] = {alo.x, alo.y, alo.z, alo.w,                        \
                       ahi.x, ahi.y, ahi.z, ahi.w};                       \
        _Pragma("unroll")                                                 \
        for (int i_ = 0; i_ < 8; i_++) {                                  \
            u64 a2 = pack2(am[i_], am[i_]);                               \
            _Pragma("unroll")                                             \
            for (int j_ = 0; j_ < 4; j_++)                                \
                acc2[i_][j_] = fma2(a2, b2[j_], acc2[i_][j_]);            \
        }                                                                 \
    } while (0)

// Transposing loader for NT operands, BK=64: thread loads 8 float4 along k,
// scatters to k-major smem rows. lr = tid>>2 (0..63), lk = (tid&3)*4.
#define LOAD_NT(Sm, Base, LD)                                             \
    do {                                                                  \
        _Pragma("unroll")                                                 \
        for (int rh_ = 0; rh_ < 2; rh_++)                                 \
            _Pragma("unroll")                                             \
            for (int kh_ = 0; kh_ < BK/16; kh_++) {                       \
                float4 v_ = *(const float4*)((Base) +                     \
                    (size_t)(lr + 64*rh_) * (LD) + k0 + lk + 16*kh_);     \
                int r_ = lr + 64*rh_;                                     \
                (Sm)[lk + 16*kh_ + 0][r_] = v_.x;                         \
                (Sm)[lk + 16*kh_ + 1][r_] = v_.y;                         \
                (Sm)[lk + 16*kh_ + 2][r_] = v_.z;                         \
                (Sm)[lk + 16*kh_ + 3][r_] = v_.w;                         \
            }                                                             \
    } while (0)

// Full-tile accumulate over one smem stage (kk unrolled x32 to bound I$).
#define COMPUTE_STAGE(As, Bs)                                             \
    do {                                                                  \
        _Pragma("unroll 32")                                              \
        for (int kk = 0; kk < BK; kk++) MICRO_STEP((As)[kk], (Bs)[kk]);   \
    } while (0)

// ---------------------------------------------------------------------------
// gemm_nt: C[m,n] = sum_k A[m,k] * B[n,k]   (A: MxK, B: NxK, row-major)
// 128x128 tile, 8x8 microtile, FFMA2. Single ascending chain (K <= 320).
// ---------------------------------------------------------------------------
__global__ void __launch_bounds__(256, 2)
gemm_nt(const float* __restrict__ A, const float* __restrict__ B,
        float* __restrict__ C, int M, int N, int K)
{
    extern __shared__ char dyn[];
    float (*As)[LDW] = (float(*)[LDW])dyn;
    float (*Bs)[LDW] = (float(*)[LDW])(dyn + BK * LDW * 4);

    const int bm = blockIdx.y << 7;
    const int bn = blockIdx.x << 7;
    const int tid = threadIdx.x;
    const int tx = tid & 15, ty = tid >> 4;
    const int lr = tid >> 2;
    const int lk = (tid & 3) << 2;

    u64 acc2[8][4];
    #pragma unroll
    for (int i = 0; i < 8; i++)
        #pragma unroll
        for (int j = 0; j < 4; j++) acc2[i][j] = 0ull;

    for (int k0 = 0; k0 < K; k0 += BK) {
        LOAD_NT(As, A + (size_t)bm * K, K);
        LOAD_NT(Bs, B + (size_t)bn * K, K);
        __syncthreads();
        COMPUTE_STAGE(As, Bs);
        __syncthreads();
    }

    #pragma unroll
    for (int i = 0; i < 8; i++) {
        int m = bm + ((i < 4) ? (ty << 2) + i : 64 + (ty << 2) + i - 4);
        ulonglong2 lo = {acc2[i][0], acc2[i][1]};
        ulonglong2 hi = {acc2[i][2], acc2[i][3]};
        *(ulonglong2*)(C + (size_t)m * N + bn + (tx << 2))      = lo;
        *(ulonglong2*)(C + (size_t)m * N + bn + 64 + (tx << 2)) = hi;
    }
}

// ---------------------------------------------------------------------------
// gemm_nt_kqv: three NT GEMMs sharing input A (hp): z picks {Wk,Wq,Wv}.
// ---------------------------------------------------------------------------
__global__ void __launch_bounds__(256, 2)
gemm_nt_kqv(const float* __restrict__ A,
            const float* __restrict__ W0, const float* __restrict__ W1,
            const float* __restrict__ W2,
            float* __restrict__ C0, float* __restrict__ C1,
            float* __restrict__ C2)
{
    const float* B = (blockIdx.z == 0) ? W0 : (blockIdx.z == 1) ? W1 : W2;
    float*       C = (blockIdx.z == 0) ? C0 : (blockIdx.z == 1) ? C1 : C2;

    extern __shared__ char dyn[];
    float (*As)[LDW] = (float(*)[LDW])dyn;
    float (*Bs)[LDW] = (float(*)[LDW])(dyn + BK * LDW * 4);

    const int bm = blockIdx.y << 7;
    const int bn = blockIdx.x << 7;
    const int tid = threadIdx.x;
    const int tx = tid & 15, ty = tid >> 4;
    const int lr = tid >> 2;
    const int lk = (tid & 3) << 2;

    u64 acc2[8][4];
    #pragma unroll
    for (int i = 0; i < 8; i++)
        #pragma unroll
        for (int j = 0; j < 4; j++) acc2[i][j] = 0ull;

    for (int k0 = 0; k0 < CDIM; k0 += BK) {
        LOAD_NT(As, A + (size_t)bm * CDIM, CDIM);
        LOAD_NT(Bs, B + (size_t)bn * CDIM, CDIM);
        __syncthreads();
        COMPUTE_STAGE(As, Bs);
        __syncthreads();
    }

    #pragma unroll
    for (int i = 0; i < 8; i++) {
        int m = bm + ((i < 4) ? (ty << 2) + i : 64 + (ty << 2) + i - 4);
        ulonglong2 lo = {acc2[i][0], acc2[i][1]};
        ulonglong2 hi = {acc2[i][2], acc2[i][3]};
        *(ulonglong2*)(C + (size_t)m * CDIM + bn + (tx << 2))      = lo;
        *(ulonglong2*)(C + (size_t)m * CDIM + bn + 64 + (tx << 2)) = hi;
    }
}

// ---------------------------------------------------------------------------
// scores: per batch b, M[t,s] = sum_c K[t,c] * Q[s,c], masked (t<s -> 0).
// ---------------------------------------------------------------------------
__global__ void __launch_bounds__(256, 2)
scores_kernel(const float* __restrict__ Kin, const float* __restrict__ Qin,
              float* __restrict__ Mout)
{
    const int bt = blockIdx.y << 7;   // t tile (output rows)
    const int bs = blockIdx.x << 7;   // s tile (output cols)
    if (bt + 127 < bs) return;        // fully upper triangle: unused

    extern __shared__ char dyn[];
    float (*As)[LDW] = (float(*)[LDW])dyn;
    float (*Bs)[LDW] = (float(*)[LDW])(dyn + BK * LDW * 4);

    const int b = blockIdx.z;
    const float* Kb = Kin + (size_t)b * NB * CDIM;
    const float* Qb = Qin + (size_t)b * NB * CDIM;
    float*       Mb = Mout + (size_t)b * NB * NB;

    const int tid = threadIdx.x;
    const int tx = tid & 15, ty = tid >> 4;
    const int lr = tid >> 2;
    const int lk = (tid & 3) << 2;

    u64 acc2[8][4];
    #pragma unroll
    for (int i = 0; i < 8; i++)
        #pragma unroll
        for (int j = 0; j < 4; j++) acc2[i][j] = 0ull;

    for (int k0 = 0; k0 < CDIM; k0 += BK) {
        LOAD_NT(As, Kb + (size_t)bt * CDIM, CDIM);
        LOAD_NT(Bs, Qb + (size_t)bs * CDIM, CDIM);
        __syncthreads();
        COMPUTE_STAGE(As, Bs);
        __syncthreads();
    }

    const bool interior = (bt >= bs + 127);   // whole tile strictly below diag
    #pragma unroll
    for (int i = 0; i < 8; i++) {
        int t = bt + ((i < 4) ? (ty << 2) + i : 64 + (ty << 2) + i - 4);
        if (interior) {
            ulonglong2 lo = {acc2[i][0], acc2[i][1]};
            ulonglong2 hi = {acc2[i][2], acc2[i][3]};
            *(ulonglong2*)(Mb + (size_t)t * NB + bs + (tx << 2))      = lo;
            *(ulonglong2*)(Mb + (size_t)t * NB + bs + 64 + (tx << 2)) = hi;
        } else {
            #pragma unroll
            for (int j = 0; j < 4; j++) {
                int s = bs + ((j < 2) ? (tx << 2) + (j << 1)
                                      : 64 + (tx << 2) + ((j - 2) << 1));
                float lo, hi;
                asm("mov.b64 {%0,%1}, %2;" : "=f"(lo), "=f"(hi) : "l"(acc2[i][j]));
                Mb[(size_t)t * NB + s]     = (t < s)     ? 0.f : lo;
                Mb[(size_t)t * NB + s + 1] = (t < s + 1) ? 0.f : hi;
            }
        }
    }
}

// ---------------------------------------------------------------------------
// av_panel: partial[j][sg][c] = sum over t in panel j (ascending FMA chain)
// of M[t,s] * V[t,c]. One CTA per (c-half, panel, s-tile, batch). M and V are
// both t-major -> straight float4 copies (no transpose). All panel spans are
// multiples of 64. t starts at max(panel_lo, bs): skipped prefix is exact
// zeros (fma no-ops).
// ---------------------------------------------------------------------------
__global__ void __launch_bounds__(256, 2)
av_panel_kernel(const float* __restrict__ Min, const float* __restrict__ Vin,
                float* __restrict__ Pp)
{
    const int jp = blockIdx.x >> 1;          // panel 0..12
    const int cc = blockIdx.x & 1;           // c half
    const int bs = blockIdx.y << 7;          // s tile base (batch-local)
    const int b  = blockIdx.z;

    const int t_lo0 = jp * KC320;
    const int t_hi  = min(t_lo0 + KC320, NB);
    const int t_lo  = max(t_lo0, bs);
    if (t_lo >= t_hi) return;                // panel entirely masked: all-zero

    extern __shared__ char dyn[];
    float (*Ms)[LDW] = (float(*)[LDW])dyn;                 // M[t][s-local]
    float (*Vs)[LDW] = (float(*)[LDW])(dyn + BK * LDW * 4);

    const int bc = cc << 7;
    const float* Mb = Min + (size_t)b * NB * NB;
    const float* Vb = Vin + (size_t)b * NB * CDIM;

    const int tid = threadIdx.x;
    const int tx = tid & 15, ty = tid >> 4;
    const int mr = tid >> 2;          // 0..63 (t-local row)
    const int mc = (tid & 3) << 2;    // 0,4,8,12

    u64 acc2[8][4];
    #pragma unroll
    for (int i = 0; i < 8; i++)
        #pragma unroll
        for (int j = 0; j < 4; j++) acc2[i][j] = 0ull;

    for (int t0 = t_lo; t0 < t_hi; t0 += BK) {
        const float* Mrow = Mb + (size_t)(t0 + mr) * NB + bs;
        const float* Vrow = Vb + (size_t)(t0 + mr) * CDIM + bc;
        #pragma unroll
        for (int jj = 0; jj < 8; jj++) {
            *(float4*)&Ms[mr][mc + 16*jj] = *(const float4*)(Mrow + mc + 16*jj);
            *(float4*)&Vs[mr][mc + 16*jj] = *(const float4*)(Vrow + mc + 16*jj);
        }
        __syncthreads();
        COMPUTE_STAGE(Ms, Vs);
        __syncthreads();
    }

    float* Pj = Pp + (size_t)jp * NBT * CDIM + (size_t)b * NB * CDIM;
    #pragma unroll
    for (int i = 0; i < 8; i++) {
        int s = bs + ((i < 4) ? (ty << 2) + i : 64 + (ty << 2) + i - 4);
        ulonglong2 lo = {acc2[i][0], acc2[i][1]};
        ulonglong2 hi = {acc2[i][2], acc2[i][3]};
        *(ulonglong2*)(Pj + (size_t)s * CDIM + bc + (tx << 2))      = lo;
        *(ulonglong2*)(Pj + (size_t)s * CDIM + bc + 64 + (tx << 2)) = hi;
    }
}

// ---------------------------------------------------------------------------
// av_combine: H[sg,c] = tanh( sum_{j ascending} partial[j][sg][c] ), RN adds
// starting from 0 -- identical sequence to the R11 flush chain (rel_err 0.0).
// jmin = bs/320 skips panels that are exact zero for the whole s-tile.
// ---------------------------------------------------------------------------
__global__ void __launch_bounds__(256)
av_combine_kernel(const float* __restrict__ Pp, float* __restrict__ Hout)
{
    const int gid = blockIdx.x * 256 + threadIdx.x;    // one float4 each
    const int sg  = gid >> 6;                          // row (0..NBT-1)
    const int c4  = (gid & 63) << 2;
    const int bs  = (sg & (NB - 1)) & ~127;            // s-tile base in batch
    const int jmin = bs / KC320;

    float4 tot = {0.f, 0.f, 0.f, 0.f};
    for (int j = jmin; j < NPANEL; j++) {
        float4 p = *(const float4*)(Pp + ((size_t)j * NBT + sg) * CDIM + c4);
        tot.x = __fadd_rn(tot.x, p.x);
        tot.y = __fadd_rn(tot.y, p.y);
        tot.z = __fadd_rn(tot.z, p.z);
        tot.w = __fadd_rn(tot.w, p.w);
    }
    float4 o;
    o.x = tanh_xla(tot.x); o.y = tanh_xla(tot.y);
    o.z = tanh_xla(tot.z); o.w = tanh_xla(tot.w);
    *(float4*)(Hout + (size_t)sg * CDIM + c4) = o;
}

// ---------------------------------------------------------------------------
extern "C" void kernel_launch(void* const* d_in, const int* in_sizes, int n_in,
                              void* d_out, int out_size)
{
    const float* x     = (const float*)d_in[0];   // (4,1,524288)
    const float* W_in  = (const float*)d_in[1];   // (256,128)
    const float* Wp    = (const float*)d_in[2];   // (4,256,256)
    const float* Wk    = (const float*)d_in[3];
    const float* Wv    = (const float*)d_in[4];
    const float* Wq    = (const float*)d_in[5];
    const float* W_out = (const float*)d_in[6];   // (128,256)
    float* out = (float*)d_out;                   // (4,4096,128)

    float *h, *hp, *kb, *qb, *vb, *mm, *pp;
    cudaGetSymbolAddress((void**)&h,  g_h);
    cudaGetSymbolAddress((void**)&hp, g_hp);
    cudaGetSymbolAddress((void**)&kb, g_k);
    cudaGetSymbolAddress((void**)&qb, g_q);
    cudaGetSymbolAddress((void**)&vb, g_v);
    cudaGetSymbolAddress((void**)&mm, g_m);
    cudaGetSymbolAddress((void**)&pp, g_pp);

    static int attr_done = 0;
    if (!attr_done) {
        cudaFuncSetAttribute(gemm_nt,
            cudaFuncAttributeMaxDynamicSharedMemorySize, TILE_SMEM);
        cudaFuncSetAttribute(gemm_nt_kqv,
            cudaFuncAttributeMaxDynamicSharedMemorySize, TILE_SMEM);
        cudaFuncSetAttribute(scores_kernel,
            cudaFuncAttributeMaxDynamicSharedMemorySize, TILE_SMEM);
        cudaFuncSetAttribute(av_panel_kernel,
            cudaFuncAttributeMaxDynamicSharedMemorySize, TILE_SMEM);
        attr_done = 1;
    }

    const dim3 blk(256);

    // Input projection: h = blocked_x @ W_in^T   (16384 x 256, K=128)
    gemm_nt<<<dim3(CDIM/128, NBT/128), blk, TILE_SMEM>>>(x, W_in, h, NBT, CDIM, 128);

    for (int l = 0; l < NLAYERS; l++) {
        const float* wp = Wp + (size_t)l * CDIM * CDIM;
        const float* wk = Wk + (size_t)l * CDIM * CDIM;
        const float* wv = Wv + (size_t)l * CDIM * CDIM;
        const float* wq = Wq + (size_t)l * CDIM * CDIM;

        // hp = h @ wp^T, then K/Q/V = hp @ {wk,wq,wv}^T batched over z
        gemm_nt<<<dim3(2, NBT/128), blk, TILE_SMEM>>>(h, wp, hp, NBT, CDIM, CDIM);
        gemm_nt_kqv<<<dim3(2, NBT/128, 3), blk, TILE_SMEM>>>(hp, wk, wq, wv, kb, qb, vb);

        // M[t,s] = k_t . q_s, tril (per batch), K=256: single panel
        scores_kernel<<<dim3(NB/128, NB/128, BATCH), blk, TILE_SMEM>>>(kb, qb, mm);

        // av panel partials (balanced grid), then ordered combine + tanh
        av_panel_kernel<<<dim3(2*NPANEL, NB/128, BATCH), blk, TILE_SMEM>>>(mm, vb, pp);
        av_combine_kernel<<<dim3(NBT*CDIM/4/256), blk>>>(pp, h);
    }

    // Output projection: out = h @ W_out^T   (16384 x 128, K=256)
    gemm_nt<<<dim3(1, NBT/128), blk, TILE_SMEM>>>(h, W_out, out, NBT, 128, CDIM);
}

// round 16
// speedup vs baseline: 1.0051x; 1.0051x over previous
#include <cuda_runtime.h>
#include <math.h>
#include <stdint.h>

// Problem constants
#define NBT    16384    // B * n_blocks (4 * 4096)
#define CDIM   256      // model channels
#define NB     4096     // blocks (tokens) per batch
#define BATCH  4
#define NLAYERS 4
#define KC320  320      // Eigen TensorContractionBlocking kc cap
#define NPANEL 13       // ceil(4096/320)

#define BK  32          // k-slice per smem stage (320 % 32 == 0)
#define LDW 132         // smem row stride in floats (528B, 16B-aligned)

typedef unsigned long long u64;

// ---------------- scratch (device globals; no runtime allocation) ----------
__device__ float g_h [NBT * CDIM];
__device__ float g_hp[NBT * CDIM];
__device__ float g_k [NBT * CDIM];
__device__ float g_q [NBT * CDIM];
__device__ float g_v [NBT * CDIM];
__device__ float g_m [(size_t)BATCH * NB * NB];        // 268 MB scores
__device__ float g_pp[(size_t)NPANEL * NBT * CDIM];    // 218 MB av panel partials

// ---------------------------------------------------------------------------
// f32x2 packed helpers: two INDEPENDENT IEEE RN ops per instruction ->
// bitwise identical to scalar fmaf / __fadd_rn on each half.
// ---------------------------------------------------------------------------
__device__ __forceinline__ u64 pack2(float lo, float hi)
{ u64 r; asm("mov.b64 %0, {%1,%2};" : "=l"(r) : "f"(lo), "f"(hi)); return r; }
__device__ __forceinline__ u64 fma2(u64 a, u64 b, u64 c)
{ u64 d; asm("fma.rn.f32x2 %0, %1, %2, %3;" : "=l"(d) : "l"(a), "l"(b), "l"(c)); return d; }

// ---------------------------------------------------------------------------
// XLA:CPU llvm_ir::EmitFastTanh, with_fma=true: clamp +-7.99881172180175781,
// FMA Horner, RN divide, |x|<4e-4 -> x (select on unclamped input).
// ---------------------------------------------------------------------------
__device__ __forceinline__ float tanh_xla(float x)
{
    const float kClamp = 7.99881172180175781f;
    float xc = fminf(fmaxf(x, -kClamp), kClamp);
    float x2 = xc * xc;
    float p = -2.76076847742355e-16f;
    p = fmaf(x2, p,  2.00018790482477e-13f);
    p = fmaf(x2, p, -8.60467152213735e-11f);
    p = fmaf(x2, p,  5.12229709037114e-08f);
    p = fmaf(x2, p,  1.48572235717979e-05f);
    p = fmaf(x2, p,  6.37261928875436e-04f);
    p = fmaf(x2, p,  4.89352455891786e-03f);
    p = xc * p;
    float q = 1.19825839466702e-06f;
    q = fmaf(x2, q, 1.18534705686654e-04f);
    q = fmaf(x2, q, 2.26843463243900e-03f);
    q = fmaf(x2, q, 4.89352518554385e-03f);
    float r = __fdiv_rn(p, q);
    return (fabsf(x) < 0.0004f) ? x : r;
}

// 8x8 microtile step: A broadcast via 2x LDS.128 + 8 pack movs, B pairs via
// 2x LDS.128. Row map i: (i<4 ? ty*4+i : 64+ty*4+i-4); col pairs j:
// {tx*4, tx*4+2, 64+tx*4, 64+tx*4+2}. Single ascending chain per output.
#define MICRO_STEP(AsRow, BsRow)                                          \
    do {                                                                  \
        float4 alo = *(const float4*)&(AsRow)[ty << 2];                   \
        float4 ahi = *(const float4*)&(AsRow)[64 + (ty << 2)];            \
        ulonglong2 blo = *(const ulonglong2*)&(BsRow)[tx << 2];           \
        ulonglong2 bhi = *(const ulonglong2*)&(BsRow)[64 + (tx << 2)];    \
        u64 b2[4] = {blo.x, blo.y, bhi.x, bhi.y};                         \
        float am[8] = {alo.x, alo.y, alo.z, alo.w,                        \
                       ahi.x, ahi.y, ahi.z, ahi.w};                       \
        _Pragma("unroll")                                                 \
        for (int i_ = 0; i_ < 8; i_++) {                                  \
            u64 a2 = pack2(am[i_], am[i_]);                               \
            _Pragma("unroll")                                             \
            for (int j_ = 0; j_ < 4; j_++)                                \
                acc2[i_][j_] = fma2(a2, b2[j_], acc2[i_][j_]);            \
        }                                                                 \
    } while (0)

#define COMPUTE_STAGE(As, Bs)                                             \
    do {                                                                  \
        _Pragma("unroll")                                                 \
        for (int kk = 0; kk < BK; kk++) MICRO_STEP((As)[kk], (Bs)[kk]);   \
    } while (0)

// Prefetch/store macros for NT operands (transpose on STS).
// lr = tid>>2 (0..63), lk = (tid&3)*4. 4 float4 per operand at BK=32.
#define LDG_NT(rg, Base, LD, K0)                                          \
    do {                                                                  \
        _Pragma("unroll")                                                 \
        for (int rh_ = 0; rh_ < 2; rh_++)                                 \
            _Pragma("unroll")                                             \
            for (int kh_ = 0; kh_ < 2; kh_++)                             \
                rg[rh_*2+kh_] = *(const float4*)((Base) +                 \
                    (size_t)(lr + 64*rh_) * (LD) + (K0) + lk + 16*kh_);   \
    } while (0)

#define STS_NT(Sm, rg)                                                    \
    do {                                                                  \
        _Pragma("unroll")                                                 \
        for (int rh_ = 0; rh_ < 2; rh_++)                                 \
            _Pragma("unroll")                                             \
            for (int kh_ = 0; kh_ < 2; kh_++) {                           \
                int r_ = lr + 64*rh_;                                     \
                (Sm)[lk + 16*kh_ + 0][r_] = rg[rh_*2+kh_].x;              \
                (Sm)[lk + 16*kh_ + 1][r_] = rg[rh_*2+kh_].y;              \
                (Sm)[lk + 16*kh_ + 2][r_] = rg[rh_*2+kh_].z;              \
                (Sm)[lk + 16*kh_ + 3][r_] = rg[rh_*2+kh_].w;              \
            }                                                             \
    } while (0)

// Prefetch/store for t-major operands (av_panel; no transpose).
// mr = tid>>3 (0..31), mc = (tid&7)*4.
#define LDG_AV(rg, Base, LD, CB, T0)                                      \
    do {                                                                  \
        _Pragma("unroll")                                                 \
        for (int jj_ = 0; jj_ < 4; jj_++)                                 \
            rg[jj_] = *(const float4*)((Base) +                           \
                (size_t)((T0) + mr) * (LD) + (CB) + mc + 32*jj_);         \
    } while (0)

#define STS_AV(Sm, rg)                                                    \
    do {                                                                  \
        _Pragma("unroll")                                                 \
        for (int jj_ = 0; jj_ < 4; jj_++)                                 \
            *(float4*)&(Sm)[mr][mc + 32*jj_] = rg[jj_];                   \
    } while (0)

// ---------------------------------------------------------------------------
// gemm_nt: C[m,n] = sum_k A[m,k] * B[n,k]   (A: MxK, B: NxK, row-major)
// 128x128 tile, 8x8 microtile, FFMA2, register-prefetch pipeline.
// ---------------------------------------------------------------------------
__global__ void __launch_bounds__(256, 2)
gemm_nt(const float* __restrict__ A, const float* __restrict__ B,
        float* __restrict__ C, int M, int N, int K)
{
    __shared__ float As[BK][LDW];
    __shared__ float Bs[BK][LDW];

    const int bm = blockIdx.y << 7;
    const int bn = blockIdx.x << 7;
    const int tid = threadIdx.x;
    const int tx = tid & 15, ty = tid >> 4;
    const int lr = tid >> 2;
    const int lk = (tid & 3) << 2;

    const float* Ab = A + (size_t)bm * K;
    const float* Bb = B + (size_t)bn * K;

    u64 acc2[8][4];
    #pragma unroll
    for (int i = 0; i < 8; i++)
        #pragma unroll
        for (int j = 0; j < 4; j++) acc2[i][j] = 0ull;

    float4 ra[4], rb[4];
    LDG_NT(ra, Ab, K, 0);
    LDG_NT(rb, Bb, K, 0);

    const int nst = K / BK;
    for (int si = 0; si < nst; si++) {
        STS_NT(As, ra);
        STS_NT(Bs, rb);
        __syncthreads();
        if (si + 1 < nst) {
            LDG_NT(ra, Ab, K, (si + 1) * BK);
            LDG_NT(rb, Bb, K, (si + 1) * BK);
        }
        COMPUTE_STAGE(As, Bs);
        __syncthreads();
    }

    #pragma unroll
    for (int i = 0; i < 8; i++) {
        int m = bm + ((i < 4) ? (ty << 2) + i : 64 + (ty << 2) + i - 4);
        ulonglong2 lo = {acc2[i][0], acc2[i][1]};
        ulonglong2 hi = {acc2[i][2], acc2[i][3]};
        *(ulonglong2*)(C + (size_t)m * N + bn + (tx << 2))      = lo;
        *(ulonglong2*)(C + (size_t)m * N + bn + 64 + (tx << 2)) = hi;
    }
}

// ---------------------------------------------------------------------------
// gemm_nt_kqv: three NT GEMMs sharing input A (hp): z picks {Wk,Wq,Wv}.
// ---------------------------------------------------------------------------
__global__ void __launch_bounds__(256, 2)
gemm_nt_kqv(const float* __restrict__ A,
            const float* __restrict__ W0, const float* __restrict__ W1,
            const float* __restrict__ W2,
            float* __restrict__ C0, float* __restrict__ C1,
            float* __restrict__ C2)
{
    const float* B = (blockIdx.z == 0) ? W0 : (blockIdx.z == 1) ? W1 : W2;
    float*       C = (blockIdx.z == 0) ? C0 : (blockIdx.z == 1) ? C1 : C2;

    __shared__ float As[BK][LDW];
    __shared__ float Bs[BK][LDW];

    const int bm = blockIdx.y << 7;
    const int bn = blockIdx.x << 7;
    const int tid = threadIdx.x;
    const int tx = tid & 15, ty = tid >> 4;
    const int lr = tid >> 2;
    const int lk = (tid & 3) << 2;

    const float* Ab = A + (size_t)bm * CDIM;
    const float* Bb = B + (size_t)bn * CDIM;

    u64 acc2[8][4];
    #pragma unroll
    for (int i = 0; i < 8; i++)
        #pragma unroll
        for (int j = 0; j < 4; j++) acc2[i][j] = 0ull;

    float4 ra[4], rb[4];
    LDG_NT(ra, Ab, CDIM, 0);
    LDG_NT(rb, Bb, CDIM, 0);

    const int nst = CDIM / BK;
    for (int si = 0; si < nst; si++) {
        STS_NT(As, ra);
        STS_NT(Bs, rb);
        __syncthreads();
        if (si + 1 < nst) {
            LDG_NT(ra, Ab, CDIM, (si + 1) * BK);
            LDG_NT(rb, Bb, CDIM, (si + 1) * BK);
        }
        COMPUTE_STAGE(As, Bs);
        __syncthreads();
    }

    #pragma unroll
    for (int i = 0; i < 8; i++) {
        int m = bm + ((i < 4) ? (ty << 2) + i : 64 + (ty << 2) + i - 4);
        ulonglong2 lo = {acc2[i][0], acc2[i][1]};
        ulonglong2 hi = {acc2[i][2], acc2[i][3]};
        *(ulonglong2*)(C + (size_t)m * CDIM + bn + (tx << 2))      = lo;
        *(ulonglong2*)(C + (size_t)m * CDIM + bn + 64 + (tx << 2)) = hi;
    }
}

// ---------------------------------------------------------------------------
// scores: per batch b, M[t,s] = sum_c K[t,c] * Q[s,c], masked (t<s -> 0).
// ---------------------------------------------------------------------------
__global__ void __launch_bounds__(256, 2)
scores_kernel(const float* __restrict__ Kin, const float* __restrict__ Qin,
              float* __restrict__ Mout)
{
    const int bt = blockIdx.y << 7;   // t tile (output rows)
    const int bs = blockIdx.x << 7;   // s tile (output cols)
    if (bt + 127 < bs) return;        // fully upper triangle: unused

    __shared__ float As[BK][LDW];
    __shared__ float Bs[BK][LDW];

    const int b = blockIdx.z;
    const float* Kb = Kin + (size_t)b * NB * CDIM + (size_t)bt * CDIM;
    const float* Qb = Qin + (size_t)b * NB * CDIM + (size_t)bs * CDIM;
    float*       Mb = Mout + (size_t)b * NB * NB;

    const int tid = threadIdx.x;
    const int tx = tid & 15, ty = tid >> 4;
    const int lr = tid >> 2;
    const int lk = (tid & 3) << 2;

    u64 acc2[8][4];
    #pragma unroll
    for (int i = 0; i < 8; i++)
        #pragma unroll
        for (int j = 0; j < 4; j++) acc2[i][j] = 0ull;

    float4 ra[4], rb[4];
    LDG_NT(ra, Kb, CDIM, 0);
    LDG_NT(rb, Qb, CDIM, 0);

    const int nst = CDIM / BK;
    for (int si = 0; si < nst; si++) {
        STS_NT(As, ra);
        STS_NT(Bs, rb);
        __syncthreads();
        if (si + 1 < nst) {
            LDG_NT(ra, Kb, CDIM, (si + 1) * BK);
            LDG_NT(rb, Qb, CDIM, (si + 1) * BK);
        }
        COMPUTE_STAGE(As, Bs);
        __syncthreads();
    }

    const bool interior = (bt >= bs + 127);   // whole tile strictly below diag
    #pragma unroll
    for (int i = 0; i < 8; i++) {
        int t = bt + ((i < 4) ? (ty << 2) + i : 64 + (ty << 2) + i - 4);
        if (interior) {
            ulonglong2 lo = {acc2[i][0], acc2[i][1]};
            ulonglong2 hi = {acc2[i][2], acc2[i][3]};
            *(ulonglong2*)(Mb + (size_t)t * NB + bs + (tx << 2))      = lo;
            *(ulonglong2*)(Mb + (size_t)t * NB + bs + 64 + (tx << 2)) = hi;
        } else {
            #pragma unroll
            for (int j = 0; j < 4; j++) {
                int s = bs + ((j < 2) ? (tx << 2) + (j << 1)
                                      : 64 + (tx << 2) + ((j - 2) << 1));
                float lo, hi;
                asm("mov.b64 {%0,%1}, %2;" : "=f"(lo), "=f"(hi) : "l"(acc2[i][j]));
                Mb[(size_t)t * NB + s]     = (t < s)     ? 0.f : lo;
                Mb[(size_t)t * NB + s + 1] = (t < s + 1) ? 0.f : hi;
            }
        }
    }
}

// ---------------------------------------------------------------------------
// av_panel: partial[j][sg][c] = sum over t in panel j (ascending FMA chain)
// of M[t,s] * V[t,c]. One CTA per (c-half, panel, s-tile, batch). M and V are
// t-major -> straight float4 copies. t starts at max(panel_lo, bs): skipped
// prefix is exact zeros (fma no-ops).
// ---------------------------------------------------------------------------
__global__ void __launch_bounds__(256, 2)
av_panel_kernel(const float* __restrict__ Min, const float* __restrict__ Vin,
                float* __restrict__ Pp)
{
    const int jp = blockIdx.x >> 1;          // panel 0..12
    const int cc = blockIdx.x & 1;           // c half
    const int bs = blockIdx.y << 7;          // s tile base (batch-local)
    const int b  = blockIdx.z;

    const int t_lo0 = jp * KC320;
    const int t_hi  = min(t_lo0 + KC320, NB);
    const int t_lo  = max(t_lo0, bs);
    if (t_lo >= t_hi) return;                // panel entirely masked: all-zero

    __shared__ float Ms[BK][LDW];            // M[t][s-local]
    __shared__ float Vs[BK][LDW];            // V[t][c-local]

    const int bc = cc << 7;
    const float* Mb = Min + (size_t)b * NB * NB;
    const float* Vb = Vin + (size_t)b * NB * CDIM;

    const int tid = threadIdx.x;
    const int tx = tid & 15, ty = tid >> 4;
    const int mr = tid >> 3;          // 0..31 (t-local row)
    const int mc = (tid & 7) << 2;    // 0,4,...,28

    u64 acc2[8][4];
    #pragma unroll
    for (int i = 0; i < 8; i++)
        #pragma unroll
        for (int j = 0; j < 4; j++) acc2[i][j] = 0ull;

    float4 rm[4], rv[4];
    LDG_AV(rm, Mb, NB, bs, t_lo);
    LDG_AV(rv, Vb, CDIM, bc, t_lo);

    for (int t0 = t_lo; t0 < t_hi; t0 += BK) {
        STS_AV(Ms, rm);
        STS_AV(Vs, rv);
        __syncthreads();
        if (t0 + BK < t_hi) {
            LDG_AV(rm, Mb, NB, bs, t0 + BK);
            LDG_AV(rv, Vb, CDIM, bc, t0 + BK);
        }
        COMPUTE_STAGE(Ms, Vs);
        __syncthreads();
    }

    float* Pj = Pp + (size_t)jp * NBT * CDIM + (size_t)b * NB * CDIM;
    #pragma unroll
    for (int i = 0; i < 8; i++) {
        int s = bs + ((i < 4) ? (ty << 2) + i : 64 + (ty << 2) + i - 4);
        ulonglong2 lo = {acc2[i][0], acc2[i][1]};
        ulonglong2 hi = {acc2[i][2], acc2[i][3]};
        *(ulonglong2*)(Pj + (size_t)s * CDIM + bc + (tx << 2))      = lo;
        *(ulonglong2*)(Pj + (size_t)s * CDIM + bc + 64 + (tx << 2)) = hi;
    }
}

// ---------------------------------------------------------------------------
// av_combine: H[sg,c] = tanh( sum_{j ascending} partial[j][sg][c] ), RN adds
// starting from 0 -- identical sequence to the R11 flush chain (rel_err 0.0).
// jmin = bs/320 skips panels that are exact zero for the whole s-tile.
// ---------------------------------------------------------------------------
__global__ void __launch_bounds__(256)
av_combine_kernel(const float* __restrict__ Pp, float* __restrict__ Hout)
{
    const int gid = blockIdx.x * 256 + threadIdx.x;    // one float4 each
    const int sg  = gid >> 6;                          // row (0..NBT-1)
    const int c4  = (gid & 63) << 2;
    const int bs  = (sg & (NB - 1)) & ~127;            // s-tile base in batch
    const int jmin = bs / KC320;

    float4 tot = {0.f, 0.f, 0.f, 0.f};
    for (int j = jmin; j < NPANEL; j++) {
        float4 p = *(const float4*)(Pp + ((size_t)j * NBT + sg) * CDIM + c4);
        tot.x = __fadd_rn(tot.x, p.x);
        tot.y = __fadd_rn(tot.y, p.y);
        tot.z = __fadd_rn(tot.z, p.z);
        tot.w = __fadd_rn(tot.w, p.w);
    }
    float4 o;
    o.x = tanh_xla(tot.x); o.y = tanh_xla(tot.y);
    o.z = tanh_xla(tot.z); o.w = tanh_xla(tot.w);
    *(float4*)(Hout + (size_t)sg * CDIM + c4) = o;
}

// ---------------------------------------------------------------------------
extern "C" void kernel_launch(void* const* d_in, const int* in_sizes, int n_in,
                              void* d_out, int out_size)
{
    const float* x     = (const float*)d_in[0];   // (4,1,524288)
    const float* W_in  = (const float*)d_in[1];   // (256,128)
    const float* Wp    = (const float*)d_in[2];   // (4,256,256)
    const float* Wk    = (const float*)d_in[3];
    const float* Wv    = (const float*)d_in[4];
    const float* Wq    = (const float*)d_in[5];
    const float* W_out = (const float*)d_in[6];   // (128,256)
    float* out = (float*)d_out;                   // (4,4096,128)

    float *h, *hp, *kb, *qb, *vb, *mm, *pp;
    cudaGetSymbolAddress((void**)&h,  g_h);
    cudaGetSymbolAddress((void**)&hp, g_hp);
    cudaGetSymbolAddress((void**)&kb, g_k);
    cudaGetSymbolAddress((void**)&qb, g_q);
    cudaGetSymbolAddress((void**)&vb, g_v);
    cudaGetSymbolAddress((void**)&mm, g_m);
    cudaGetSymbolAddress((void**)&pp, g_pp);

    const dim3 blk(256);

    // Input projection: h = blocked_x @ W_in^T   (16384 x 256, K=128)
    gemm_nt<<<dim3(CDIM/128, NBT/128), blk>>>(x, W_in, h, NBT, CDIM, 128);

    for (int l = 0; l < NLAYERS; l++) {
        const float* wp = Wp + (size_t)l * CDIM * CDIM;
        const float* wk = Wk + (size_t)l * CDIM * CDIM;
        const float* wv = Wv + (size_t)l * CDIM * CDIM;
        const float* wq = Wq + (size_t)l * CDIM * CDIM;

        // hp = h @ wp^T, then K/Q/V = hp @ {wk,wq,wv}^T batched over z
        gemm_nt<<<dim3(2, NBT/128), blk>>>(h, wp, hp, NBT, CDIM, CDIM);
        gemm_nt_kqv<<<dim3(2, NBT/128, 3), blk>>>(hp, wk, wq, wv, kb, qb, vb);

        // M[t,s] = k_t . q_s, tril (per batch), K=256: single panel
        scores_kernel<<<dim3(NB/128, NB/128, BATCH), blk>>>(kb, qb, mm);

        // av panel partials (balanced grid), then ordered combine + tanh
        av_panel_kernel<<<dim3(2*NPANEL, NB/128, BATCH), blk>>>(mm, vb, pp);
        av_combine_kernel<<<dim3(NBT*CDIM/4/256), blk>>>(pp, h);
    }

    // Output projection: out = h @ W_out^T   (16384 x 128, K=256)
    gemm_nt<<<dim3(1, NBT/128), blk>>>(h, W_out, out, NBT, 128, CDIM);
}